// round 15
// baseline (speedup 1.0000x reference)
#include <cuda_runtime.h>
#include <cuda_fp16.h>
#include <cstdint>

// Problem constants
#define Bz   8192
#define Tz   512
#define Dz   8
#define Hz   64
#define Gz   256      // 4*H
#define BT   64       // batch tile per CTA
#define NCTA 128      // Bz / BT
#define NTHR 512

#define KPX  88       // xin kpad (halves) -> conflict-free ldmatrix rows
#define KPH  72       // h   kpad (halves) -> conflict-free ldmatrix rows
#define GSW  36       // gate tile row stride (floats), tile = [32 batch][36]

// ---- SMEM byte offsets ----
#define GS_OFF   0                    // per-warp gate tiles: 16 * 32*36*4 = 73728
#define XHI_OFF  73728                // half x[64][KPX]   11264
#define XLO_OFF  84992
#define H_OFF    96256                // 12 bufs (3 layer x 2 parity x hi/lo) of 64*KPH*2 = 9216
#define FW_OFF   206848               // fp32 fcW[8][64]   2048
#define FB_OFF   208896               // fp32 fcb          64
#define SB_OFF   208960               // fp32 permuted bias[6][256]  6144
#define SMEM_BYTES 215104

#define HBUF_B   9216

// ---- weight fragment arenas (A-frag order, PERMUTED rows), hi/lo split ----
// element index = base + kt*512 + mt*32 + lane ; input matrix then hidden matrix contiguous
#define NW 23552
__device__ uint4 g_whi[NW];
__device__ uint4 g_wlo[NW];

// per-matrix bases (uint4 units): kts = {1,4,4,4,4,4, 5,4,4,4,4,4}
#define B_EI0 0
#define B_EH0 512
#define B_EI1 2560
#define B_EH1 4608
#define B_EI2 6656
#define B_EH2 8704
#define B_DI0 10752
#define B_DH0 13312
#define B_DI1 15360
#define B_DH1 17408
#define B_DI2 19456
#define B_DH2 21504

// per-CTA, per-layer fp32 c-state in global (L2-resident): [cta][layer][u*64+b]
__device__ float g_c[NCTA * 3 * 64 * 64];

// ---------------- helpers ----------------
__device__ __forceinline__ float tanhx(float x) {
    float r;
    asm("tanh.approx.f32 %0, %1;" : "=f"(r) : "f"(x));
    return r;
}
__device__ __forceinline__ float sigx(float x) {
    return fmaf(tanhx(0.5f * x), 0.5f, 0.5f);
}
__device__ __forceinline__ void mma16816(float c[4], uint4 a, unsigned b0, unsigned b1) {
    asm volatile("mma.sync.aligned.m16n8k16.row.col.f32.f16.f16.f32 "
                 "{%0,%1,%2,%3}, {%4,%5,%6,%7}, {%8,%9}, {%0,%1,%2,%3};"
                 : "+f"(c[0]), "+f"(c[1]), "+f"(c[2]), "+f"(c[3])
                 : "r"(a.x), "r"(a.y), "r"(a.z), "r"(a.w), "r"(b0), "r"(b1));
}
__device__ __forceinline__ void ldsm_x4(unsigned r[4], uint32_t addr) {
    asm volatile("ldmatrix.sync.aligned.m8n8.x4.shared.b16 {%0,%1,%2,%3}, [%4];"
                 : "=r"(r[0]), "=r"(r[1]), "=r"(r[2]), "=r"(r[3]) : "r"(addr));
}
__device__ __forceinline__ uint32_t smem_u32(const void* p) {
    return (uint32_t)__cvta_generic_to_shared(p);
}
__device__ __forceinline__ void split16(float v, __half& hi, __half& lo) {
    hi = __float2half_rn(v);
    lo = __float2half_rn(v - __half2float(hi));
}

// ---------------- weight prep (one launch), with gate-row permutation ----------------
// permuted row p: unit = p>>2, gate = p&3  =>  source row = 64*(p&3) + (p>>2)
__global__ void prep_all(const float* __restrict__ p0, const float* __restrict__ p1,
                         const float* __restrict__ p2, const float* __restrict__ p3,
                         const float* __restrict__ p4, const float* __restrict__ p5,
                         const float* __restrict__ p6, const float* __restrict__ p7,
                         const float* __restrict__ p8, const float* __restrict__ p9,
                         const float* __restrict__ p10, const float* __restrict__ p11) {
    int id = blockIdx.x * 256 + threadIdx.x;
    if (id >= NW) return;
    const int kts[12]  = {1,4,4,4,4,4, 5,4,4,4,4,4};
    const int fans[12] = {8,64,64,64,64,64, 72,64,64,64,64,64};
    const float* ptrs[12] = {p0,p1,p2,p3,p4,p5,p6,p7,p8,p9,p10,p11};
    int m = 0, rel = id;
    #pragma unroll
    for (int i = 0; i < 12; ++i) {
        int sz = kts[i] * 512;
        if (rel >= sz && m == i) { rel -= sz; m = i + 1; }
    }
    int kt = rel >> 9, slot = rel & 511, mt = slot >> 5, lane = slot & 31;
    int fan = fans[m];
    const float* W = ptrs[m];
    unsigned hi4[4], lo4[4];
    #pragma unroll
    for (int r = 0; r < 4; ++r) {
        int prow = mt * 16 + (lane >> 2) + (r & 1) * 8;
        int srow = 64 * (prow & 3) + (prow >> 2);      // gate-row permutation
        int c0   = kt * 16 + (lane & 3) * 2 + (r >> 1) * 8;
        float w0 = (c0 < fan)     ? W[srow * fan + c0]     : 0.f;
        float w1 = (c0 + 1 < fan) ? W[srow * fan + c0 + 1] : 0.f;
        __half h0, l0, h1, l1;
        split16(w0, h0, l0);
        split16(w1, h1, l1);
        hi4[r] = (unsigned)__half_as_ushort(h0) | ((unsigned)__half_as_ushort(h1) << 16);
        lo4[r] = (unsigned)__half_as_ushort(l0) | ((unsigned)__half_as_ushort(l1) << 16);
    }
    g_whi[id] = make_uint4(hi4[0], hi4[1], hi4[2], hi4[3]);
    g_wlo[id] = make_uint4(lo4[0], lo4[1], lo4[2], lo4[3]);
}

// lane-specific ldmatrix base address (bytes) for kt=0, n-rows [nb, nb+16)
__device__ __forceinline__ uint32_t ldsm_base(const __half* B, int kpad, int nb, int lane) {
    int r8 = lane & 7, kh = (lane >> 3) & 1, nh = (lane >> 4) & 1;
    int off = (nb + r8 + nh * 8) * kpad + kh * 8;
    return smem_u32(B) + (uint32_t)off * 2;
}

// ---------------- fused layer: unified MMA loop + warp-local LSTM epilogue ----------------
// A arena: input-matrix kts followed contiguously by hidden-matrix kts (4).
// Warp w: m-tiles {2(w>>1), 2(w>>1)+1}, batches [32(w&1), +32).
template<int NKTI, bool HAS_Y>
__device__ __forceinline__ void layer(int tid,
                                      const uint4* __restrict__ Ahi, const uint4* __restrict__ Alo,
                                      const __half* __restrict__ BIhi, const __half* __restrict__ BIlo, int kpadIn,
                                      const __half* __restrict__ BHhi, const __half* __restrict__ BHlo,
                                      const float* __restrict__ sbP,
                                      float* __restrict__ cg, bool first,
                                      __half* __restrict__ Hhi, __half* __restrict__ Hlo,
                                      __half* Yhi, __half* Ylo,
                                      float* __restrict__ gsAll) {
    const int w = tid >> 5, lane = tid & 31;
    const int mtg = (w >> 1) * 2, nb = (w & 1) * 32;
    const int r = lane >> 2, q = lane & 3;
    float* gsw = gsAll + w * (32 * GSW);
    constexpr int NKT = NKTI + 4;

    // epilogue lane mapping: lane -> (local unit ul, batch group bg)
    const int ul = lane & 7, bg = lane >> 3;
    const int U  = 8 * (w >> 1) + ul;     // global unit
    const int nbb = nb + 8 * bg;          // base batch (8 contiguous)

    // c-state prefetch (global, L2-resident; latency hides under MMA)
    float4 cA, cB;
    if (first) { cA = make_float4(0.f, 0.f, 0.f, 0.f); cB = cA; }
    else { cA = *(const float4*)(cg + U * 64 + nbb);
           cB = *(const float4*)(cg + U * 64 + nbb + 4); }

    // B ldmatrix addresses (input-buffer set and hidden-buffer set)
    uint32_t xh0 = ldsm_base(BIhi, kpadIn, nb, lane), xh1 = xh0 + (uint32_t)(16 * kpadIn * 2);
    uint32_t xl0 = ldsm_base(BIlo, kpadIn, nb, lane), xl1 = xl0 + (uint32_t)(16 * kpadIn * 2);
    uint32_t hh0 = ldsm_base(BHhi, KPH, nb, lane),    hh1 = hh0 + (uint32_t)(16 * KPH * 2);
    uint32_t hl0 = ldsm_base(BHlo, KPH, nb, lane),    hl1 = hl0 + (uint32_t)(16 * KPH * 2);

    // A streams: unified contiguous kt index 0..NKT-1
    const uint4* p0h = Ahi + mtg * 32 + lane;  const uint4* p1h = p0h + 32;
    const uint4* p0l = Alo + mtg * 32 + lane;  const uint4* p1l = p0l + 32;
    uint4 a0h = p0h[0], a1h = p1h[0], a0l = p0l[0], a1l = p1l[0];

    float c[2][4][4];
    #pragma unroll
    for (int mt = 0; mt < 2; ++mt) {
        float bA = sbP[(mtg + mt) * 16 + r], bB = sbP[(mtg + mt) * 16 + r + 8];
        #pragma unroll
        for (int ntp = 0; ntp < 4; ++ntp) {
            c[mt][ntp][0] = bA; c[mt][ntp][1] = bA;
            c[mt][ntp][2] = bB; c[mt][ntp][3] = bB;
        }
    }

    #pragma unroll
    for (int kt = 0; kt < NKT; ++kt) {
        uint4 A0h = a0h, A1h = a1h, A0l = a0l, A1l = a1l;
        if (kt + 1 < NKT) {
            a0h = p0h[(kt + 1) * 512]; a1h = p1h[(kt + 1) * 512];
            a0l = p0l[(kt + 1) * 512]; a1l = p1l[(kt + 1) * 512];
        }
        // B addresses: input buffer for kt < NKTI, hidden buffer after (compile-time select)
        uint32_t bH0, bH1, bL0, bL1;
        if (kt < NKTI) {
            bH0 = xh0 + (uint32_t)kt * 32; bH1 = xh1 + (uint32_t)kt * 32;
            bL0 = xl0 + (uint32_t)kt * 32; bL1 = xl1 + (uint32_t)kt * 32;
        } else {
            bH0 = hh0 + (uint32_t)(kt - NKTI) * 32; bH1 = hh1 + (uint32_t)(kt - NKTI) * 32;
            bL0 = hl0 + (uint32_t)(kt - NKTI) * 32; bL1 = hl1 + (uint32_t)(kt - NKTI) * 32;
        }
        unsigned bh[8], bl[8];
        ldsm_x4(bh,     bH0);
        ldsm_x4(bh + 4, bH1);
        ldsm_x4(bl,     bL0);
        ldsm_x4(bl + 4, bL1);
        #pragma unroll
        for (int ntp = 0; ntp < 4; ++ntp) {
            unsigned h0 = bh[2 * ntp], h1 = bh[2 * ntp + 1];
            unsigned l0 = bl[2 * ntp], l1 = bl[2 * ntp + 1];
            mma16816(c[0][ntp], A0h, h0, h1);
            mma16816(c[0][ntp], A0l, h0, h1);
            mma16816(c[0][ntp], A0h, l0, l1);
            mma16816(c[1][ntp], A1h, h0, h1);
            mma16816(c[1][ntp], A1l, h0, h1);
            mma16816(c[1][ntp], A1h, l0, l1);
        }
    }

    // gates -> transposed warp tile T[batch 0..31][row 0..31], stride GSW.
    // Conflict-free: per instr bank = (8q + r + const) % 32, distinct over lanes.
    #pragma unroll
    for (int mt = 0; mt < 2; ++mt)
        #pragma unroll
        for (int ntp = 0; ntp < 4; ++ntp) {
            int col0 = 8 * ntp + 2 * q;
            gsw[(col0    ) * GSW + 16 * mt + r    ] = c[mt][ntp][0];
            gsw[(col0 + 1) * GSW + 16 * mt + r    ] = c[mt][ntp][1];
            gsw[(col0    ) * GSW + 16 * mt + r + 8] = c[mt][ntp][2];
            gsw[(col0 + 1) * GSW + 16 * mt + r + 8] = c[mt][ntp][3];
        }
    __syncwarp();

    // epilogue: lane owns unit U x 8 contiguous batches; 4 gates arrive as one float4
    float cc[8] = {cA.x, cA.y, cA.z, cA.w, cB.x, cB.y, cB.z, cB.w};
    #pragma unroll
    for (int bi = 0; bi < 8; ++bi) {
        float4 g4 = *(const float4*)(gsw + (8 * bg + bi) * GSW + 4 * ul);  // i,f,g,o
        float cn = sigx(g4.y) * cc[bi] + sigx(g4.x) * tanhx(g4.z);
        float hn = sigx(g4.w) * tanhx(cn);
        cc[bi] = cn;
        __half hi, lo; split16(hn, hi, lo);
        Hhi[(nbb + bi) * KPH + U] = hi;
        Hlo[(nbb + bi) * KPH + U] = lo;
        if (HAS_Y) { Yhi[(nbb + bi) * KPX + U] = hi; Ylo[(nbb + bi) * KPX + U] = lo; }
    }
    *(float4*)(cg + U * 64 + nbb)     = make_float4(cc[0], cc[1], cc[2], cc[3]);
    *(float4*)(cg + U * 64 + nbb + 4) = make_float4(cc[4], cc[5], cc[6], cc[7]);
}

// x staging: 512 threads = 64 batches x 8 cols
__device__ __forceinline__ void stage_x(int tid, const float* __restrict__ xp,
                                        int b0, int t, __half* xhi, __half* xlo) {
    int b = tid & 63, k = tid >> 6;
    float v = xp[((size_t)(b0 + b) * Tz + t) * Dz + k];
    __half hi, lo; split16(v, hi, lo);
    xhi[b * KPX + k] = hi; xlo[b * KPX + k] = lo;
}

// fc for step t: reads h2 (hi+lo) buffers of given parity
__device__ __forceinline__ void fc_do(int tid, const __half* __restrict__ h2hi,
                                      const __half* __restrict__ h2lo,
                                      const float* __restrict__ fw,
                                      const float* __restrict__ fb,
                                      float* __restrict__ out, int b0, int t) {
    int d = tid & 7, b = tid >> 3;
    float a = fb[d];
    #pragma unroll
    for (int u2 = 0; u2 < 32; ++u2) {
        __half2 hh = *(const __half2*)(h2hi + b * KPH + 2 * u2);
        __half2 hl = *(const __half2*)(h2lo + b * KPH + 2 * u2);
        float2 fh = __half22float2(hh), fl = __half22float2(hl);
        a = fmaf(fw[d * 64 + 2 * u2],     fh.x + fl.x, a);
        a = fmaf(fw[d * 64 + 2 * u2 + 1], fh.y + fl.y, a);
    }
    out[((size_t)(b0 + b) * Tz + t) * Dz + d] = a;
}

__global__ void __launch_bounds__(NTHR, 1)
seq2seq_kernel(const float* __restrict__ enc_x, const float* __restrict__ dec_x,
               const float* __restrict__ eb0, const float* __restrict__ eb1, const float* __restrict__ eb2,
               const float* __restrict__ db0, const float* __restrict__ db1, const float* __restrict__ db2,
               const float* __restrict__ fcW, const float* __restrict__ fcb,
               float* __restrict__ out) {
    extern __shared__ __align__(16) char sm[];
    float* gs   = (float*)(sm + GS_OFF);
    __half* xhi = (__half*)(sm + XHI_OFF);
    __half* xlo = (__half*)(sm + XLO_OFF);
    float* fw = (float*)(sm + FW_OFF);
    float* fb = (float*)(sm + FB_OFF);
    float* sb = (float*)(sm + SB_OFF);

    const int tid = threadIdx.x;
    const int b0  = blockIdx.x * BT;

    // h buffer accessor: layer l, parity par, hi/lo
    __half* hb[3][2][2];
    #pragma unroll
    for (int l = 0; l < 3; ++l)
        #pragma unroll
        for (int par = 0; par < 2; ++par)
            #pragma unroll
            for (int hl = 0; hl < 2; ++hl)
                hb[l][par][hl] = (__half*)(sm + H_OFF + (((l * 2 + par) * 2 + hl) * HBUF_B));

    float* cg0 = g_c + ((size_t)blockIdx.x * 3 + 0) * 4096;
    float* cg1 = g_c + ((size_t)blockIdx.x * 3 + 1) * 4096;
    float* cg2 = g_c + ((size_t)blockIdx.x * 3 + 2) * 4096;

    // init: zero x + all h buffers, cache fc + permuted biases
    {
        uint32_t* xz = (uint32_t*)(sm + XHI_OFF);
        for (int i = tid; i < (2 * BT * KPX) / 2; i += NTHR) xz[i] = 0u;
        uint32_t* hz = (uint32_t*)(sm + H_OFF);
        for (int i = tid; i < (12 * HBUF_B) / 4; i += NTHR) hz[i] = 0u;
        for (int i = tid; i < Dz * Hz; i += NTHR) fw[i] = fcW[i];
        if (tid < Dz) fb[tid] = fcb[tid];
        for (int i = tid; i < Gz; i += NTHR) {
            int srow = 64 * (i & 3) + (i >> 2);        // permuted bias
            sb[i]            = eb0[srow];
            sb[Gz + i]       = eb1[srow];
            sb[2 * Gz + i]   = eb2[srow];
            sb[3 * Gz + i]   = db0[srow];
            sb[4 * Gz + i]   = db1[srow];
            sb[5 * Gz + i]   = db2[srow];
        }
        stage_x(tid, enc_x, b0, 0, xhi, xlo);
    }
    __syncthreads();

    // ---------------- encoder ----------------
    #pragma unroll 1
    for (int t = 0; t < Tz; ++t) {
        const int p = t & 1;
        layer<1, false>(tid, g_whi + B_EI0, g_wlo + B_EI0, xhi, xlo, KPX,
                        hb[0][p][0], hb[0][p][1], sb, cg0, t == 0,
                        hb[0][1 - p][0], hb[0][1 - p][1], (__half*)0, (__half*)0, gs);
        __syncthreads();
        layer<4, false>(tid, g_whi + B_EI1, g_wlo + B_EI1, hb[0][1 - p][0], hb[0][1 - p][1], KPH,
                        hb[1][p][0], hb[1][p][1], sb + Gz, cg1, false,
                        hb[1][1 - p][0], hb[1][1 - p][1], (__half*)0, (__half*)0, gs);
        __syncthreads();
        if (t < Tz - 1) stage_x(tid, enc_x, b0, t + 1, xhi, xlo);
        else            stage_x(tid, dec_x, b0, 0, xhi, xlo);
        layer<4, false>(tid, g_whi + B_EI2, g_wlo + B_EI2, hb[1][1 - p][0], hb[1][1 - p][1], KPH,
                        hb[2][p][0], hb[2][p][1], sb + 2 * Gz, cg2, false,
                        hb[2][1 - p][0], hb[2][1 - p][1], (__half*)0, (__half*)0, gs);
        __syncthreads();
    }

    // ---------------- decoder ----------------
    // encoder last write parity = 0; dec t=0 reads p=0. y_prev cols zeroed at init.
    #pragma unroll 1
    for (int t = 0; t < Tz; ++t) {
        const int p = t & 1;
        layer<5, false>(tid, g_whi + B_DI0, g_wlo + B_DI0, xhi, xlo, KPX,
                        hb[0][p][0], hb[0][p][1], sb + 3 * Gz, cg0, false,
                        hb[0][1 - p][0], hb[0][1 - p][1], (__half*)0, (__half*)0, gs);
        if (t > 0) fc_do(tid, hb[2][p][0], hb[2][p][1], fw, fb, out, b0, t - 1);
        __syncthreads();
        layer<4, false>(tid, g_whi + B_DI1, g_wlo + B_DI1, hb[0][1 - p][0], hb[0][1 - p][1], KPH,
                        hb[1][p][0], hb[1][p][1], sb + 4 * Gz, cg1, false,
                        hb[1][1 - p][0], hb[1][1 - p][1], (__half*)0, (__half*)0, gs);
        __syncthreads();
        if (t < Tz - 1) stage_x(tid, dec_x, b0, t + 1, xhi, xlo);
        layer<4, true>(tid, g_whi + B_DI2, g_wlo + B_DI2, hb[1][1 - p][0], hb[1][1 - p][1], KPH,
                       hb[2][p][0], hb[2][p][1], sb + 5 * Gz, cg2, false,
                       hb[2][1 - p][0], hb[2][1 - p][1], xhi + 8, xlo + 8, gs);
        __syncthreads();
    }
    // final output: t = 511 written at parity 0
    fc_do(tid, hb[2][0][0], hb[2][0][1], fw, fb, out, b0, Tz - 1);
}

extern "C" void kernel_launch(void* const* d_in, const int* in_sizes, int n_in,
                              void* d_out, int out_size) {
    (void)in_sizes; (void)n_in; (void)out_size;
    const float* enc_x = (const float*)d_in[0];
    const float* dec_x = (const float*)d_in[1];
    const float* eWih0 = (const float*)d_in[2];
    const float* eWhh0 = (const float*)d_in[3];
    const float* eb0   = (const float*)d_in[4];
    const float* eWih1 = (const float*)d_in[5];
    const float* eWhh1 = (const float*)d_in[6];
    const float* eb1   = (const float*)d_in[7];
    const float* eWih2 = (const float*)d_in[8];
    const float* eWhh2 = (const float*)d_in[9];
    const float* eb2   = (const float*)d_in[10];
    const float* dWih0 = (const float*)d_in[11];
    const float* dWhh0 = (const float*)d_in[12];
    const float* db0   = (const float*)d_in[13];
    const float* dWih1 = (const float*)d_in[14];
    const float* dWhh1 = (const float*)d_in[15];
    const float* db1   = (const float*)d_in[16];
    const float* dWih2 = (const float*)d_in[17];
    const float* dWhh2 = (const float*)d_in[18];
    const float* db2   = (const float*)d_in[19];
    const float* fcW   = (const float*)d_in[20];
    const float* fcb   = (const float*)d_in[21];
    float* out = (float*)d_out;

    // fragment-order hi/lo weight prep with gate-row permutation (ONE launch)
    prep_all<<<92, 256>>>(eWih0, eWhh0, eWih1, eWhh1, eWih2, eWhh2,
                          dWih0, dWhh0, dWih1, dWhh1, dWih2, dWhh2);

    cudaFuncSetAttribute(seq2seq_kernel,
                         cudaFuncAttributeMaxDynamicSharedMemorySize, SMEM_BYTES);
    seq2seq_kernel<<<NCTA, NTHR, SMEM_BYTES>>>(
        enc_x, dec_x, eb0, eb1, eb2, db0, db1, db2, fcW, fcb, out);
}